// round 6
// baseline (speedup 1.0000x reference)
#include <cuda_runtime.h>

typedef unsigned long long ull;

#define BB   256
#define TT   2000
#define FIN  42
#define FINP 44
#define HH   24
#define G3   72
#define ROWS (BB * TT)
#define UU   8
#define PH2B 64
#define ALLF 0x0101010101010101ULL

// scratch: xg[row][72] gate preacts (147.5 MB), h[B,T,24] (49 MB), t-flags
__device__ float g_xg[(size_t)ROWS * G3];
__device__ float g_h[(size_t)ROWS * HH];
__device__ __align__(8) unsigned char g_flag[TT + 64];

__device__ __forceinline__ float tanh_a(float x) {
    float y; asm("tanh.approx.f32 %0, %1;" : "=f"(y) : "f"(x)); return y;
}
__device__ __forceinline__ ull fma2(ull a, ull b, ull c) {
    ull d; asm("fma.rn.f32x2 %0, %1, %2, %3;" : "=l"(d) : "l"(a), "l"(b), "l"(c)); return d;
}
__device__ __forceinline__ ull add2(ull a, ull b) {
    ull d; asm("add.rn.f32x2 %0, %1, %2;" : "=l"(d) : "l"(a), "l"(b)); return d;
}
__device__ __forceinline__ ull pack2(float lo, float hi) {
    ull d; asm("mov.b64 %0, {%1, %2};" : "=l"(d) : "f"(lo), "f"(hi)); return d;
}
__device__ __forceinline__ float2 unpack2(ull v) {
    float2 r; asm("mov.b64 {%0, %1}, %2;" : "=f"(r.x), "=f"(r.y) : "l"(v)); return r;
}
__device__ __forceinline__ float hsum2(ull v) {
    float2 r = unpack2(v); return r.x + r.y;
}
__device__ __forceinline__ ull ld_acq(const ull* p) {
    ull v; asm volatile("ld.acquire.gpu.global.u64 %0, [%1];" : "=l"(v) : "l"(p) : "memory");
    return v;
}
__device__ __forceinline__ void wait_q(const ull* p) {
    while (ld_acq(p) != ALLF) __nanosleep(64);
}

__global__ void vad_zero() {
    int i = threadIdx.x;
    if (i < (TT + 64) / 8) ((ull*)g_flag)[i] = 0ULL;
}

// ---------------------------------------------------------------------------
// Fused kernel. Blocks [0,64): consumer (4 GRU warps each, one batch row per
// warp). Blocks [64, 64+2000): producer — block g computes xg for timestep
// t = g-64 across all 256 batches, then raises flag[t].
// ---------------------------------------------------------------------------
__global__ __launch_bounds__(128) void vad_fused(
    const float* __restrict__ x, const float* __restrict__ lc1_w,
    const float* __restrict__ lc1_b, const float* __restrict__ w_ih,
    const float* __restrict__ b_ih, const float* __restrict__ w_hh,
    const float* __restrict__ b_hh)
{
    __shared__ __align__(16) float s_w1[HH * FINP];
    __shared__ float s_b1[HH];
    __shared__ __align__(16) ull s_wi2[G3 * 12];
    __shared__ float s_cb[G3];
    __shared__ __align__(16) float s_h[4][2][32];

    int tid = threadIdx.x;

    if (blockIdx.x < PH2B) {
        // ---------------- consumer: GRU recurrence ----------------
        int wid = tid >> 5, lane = tid & 31;
        int b = blockIdx.x * 4 + wid;
        int i = (lane < HH) ? lane : 0;

        const ull* w8 = (const ull*)w_hh;
        ull wr2[12], wz2[12], wn2[12];
#pragma unroll
        for (int k = 0; k < 12; k++) {
            float2 r = unpack2(w8[(0 * HH + i) * 12 + k]);
            wr2[k] = pack2(0.5f * r.x, 0.5f * r.y);
            float2 z = unpack2(w8[(1 * HH + i) * 12 + k]);
            wz2[k] = pack2(0.5f * z.x, 0.5f * z.y);
            wn2[k] = w8[(2 * HH + i) * 12 + k];
        }
        ull bn2 = pack2(b_hh[2 * HH + i], 0.0f);

        const float* xgp = g_xg + (size_t)b * TT * G3;
        float* hp = g_h + (size_t)b * TT * HH;
        const ull* fq = (const ull*)g_flag;

        // first two chunks must be ready before initial loads
        wait_q(fq + 0);
        wait_q(fq + 1);

        float h = 0.0f;
        float cr[UU], cz[UU], cn[UU];
#pragma unroll
        for (int u = 0; u < UU; u++) {
            cr[u] = __ldcg(xgp + u * G3 + 0 * HH + i);
            cz[u] = __ldcg(xgp + u * G3 + 1 * HH + i);
            cn[u] = __ldcg(xgp + u * G3 + 2 * HH + i);
        }

        for (int t0 = 0; t0 < TT; t0 += UU) {
            // prefetch next chunk (flags for it were confirmed last iteration)
            float nr[UU], nz[UU], nn[UU];
            bool more = (t0 + UU) < TT;
            const float* np = xgp + (size_t)(t0 + UU) * G3;
#pragma unroll
            for (int u = 0; u < UU; u++) {
                nr[u] = more ? __ldcg(np + u * G3 + 0 * HH + i) : 0.0f;
                nz[u] = more ? __ldcg(np + u * G3 + 1 * HH + i) : 0.0f;
                nn[u] = more ? __ldcg(np + u * G3 + 2 * HH + i) : 0.0f;
            }

            // early acquire-read of the flags guarding NEXT iteration's
            // prefetch; branch-checked only after the 8-step compute below.
            bool need = (t0 + 2 * UU) < TT;
            ull f = need ? ld_acq(fq + ((t0 + 2 * UU) >> 3)) : ALLF;

#pragma unroll
            for (int u = 0; u < UU; u++) {
                int pb = u & 1;
                s_h[wid][pb][lane] = h;
                __syncwarp();
                ull h2[12];
                {
                    const ulonglong2* sh2 = (const ulonglong2*)&s_h[wid][pb][0];
#pragma unroll
                    for (int k = 0; k < 6; k++) {
                        ulonglong2 t = sh2[k];
                        h2[2 * k] = t.x; h2[2 * k + 1] = t.y;
                    }
                }
                ull ra = pack2(cr[u], 0.0f), rb = 0ULL;
                ull za = pack2(cz[u], 0.0f), zb = 0ULL;
                ull na = bn2, nb2 = 0ULL;
#pragma unroll
                for (int m = 0; m < 6; m++) {
                    ra  = fma2(wr2[2 * m],     h2[2 * m],     ra);
                    rb  = fma2(wr2[2 * m + 1], h2[2 * m + 1], rb);
                    za  = fma2(wz2[2 * m],     h2[2 * m],     za);
                    zb  = fma2(wz2[2 * m + 1], h2[2 * m + 1], zb);
                    na  = fma2(wn2[2 * m],     h2[2 * m],     na);
                    nb2 = fma2(wn2[2 * m + 1], h2[2 * m + 1], nb2);
                }
                float hr = hsum2(add2(ra, rb));
                float hz = hsum2(add2(za, zb));
                float hn = hsum2(add2(na, nb2));

                float r = fmaf(tanh_a(hr), 0.5f, 0.5f);
                float z = fmaf(tanh_a(hz), 0.5f, 0.5f);
                float n = tanh_a(fmaf(r, hn, cn[u]));
                h = fmaf(z, h - n, n);

                if (lane < HH) hp[(t0 + u) * HH + lane] = h;
            }

            if (need && f != ALLF) wait_q(fq + ((t0 + 2 * UU) >> 3));

#pragma unroll
            for (int u = 0; u < UU; u++) { cr[u] = nr[u]; cz[u] = nz[u]; cn[u] = nn[u]; }
        }
        return;
    }

    // ---------------- producer: xg for timestep t, all batches ----------------
    int t = blockIdx.x - PH2B;

    for (int i = tid; i < HH * FINP; i += 128) {
        int h = i / FINP, f = i - h * FINP;
        s_w1[i] = (f < FIN) ? lc1_w[h * FIN + f] : 0.0f;
    }
    const ull* wi8 = (const ull*)w_ih;
    for (int i = tid; i < G3 * 12; i += 128) {
        ull w = wi8[i];
        if (i < 48 * 12) {                 // r,z rows pre-halved
            float2 f = unpack2(w);
            w = pack2(0.5f * f.x, 0.5f * f.y);
        }
        s_wi2[i] = w;
    }
    if (tid < G3) {
        float b = b_ih[tid];
        s_cb[tid] = (tid < 48) ? 0.5f * (b + b_hh[tid]) : b;
    }
    if (tid < HH) s_b1[tid] = lc1_b[tid];
    __syncthreads();

    // two batches per thread: b = tid and tid+128, row = b*TT + t
    size_t rA = (size_t)tid * TT + t;
    size_t rB = (size_t)(tid + 128) * TT + t;
    const ull* xA = (const ull*)(x + rA * FIN);
    const ull* xB = (const ull*)(x + rB * FIN);

    ull xpA[22], xpB[22];
#pragma unroll
    for (int q = 0; q < 21; q++) { xpA[q] = xA[q]; xpB[q] = xB[q]; }
    xpA[21] = 0ULL; xpB[21] = 0ULL;

    float aA[HH], aB[HH];
#pragma unroll
    for (int h = 0; h < HH; h++) {
        const ulonglong2* wv = (const ulonglong2*)&s_w1[h * FINP];
        float b = s_b1[h];
        ull pA = pack2(b, 0.0f), qA = 0ULL, pB = pack2(b, 0.0f), qB = 0ULL;
#pragma unroll
        for (int m = 0; m < 11; m++) {
            ulonglong2 w = wv[m];
            pA = fma2(w.x, xpA[2 * m], pA);
            qA = fma2(w.y, xpA[2 * m + 1], qA);
            pB = fma2(w.x, xpB[2 * m], pB);
            qB = fma2(w.y, xpB[2 * m + 1], qB);
        }
        aA[h] = tanh_a(hsum2(add2(pA, qA)));
        aB[h] = tanh_a(hsum2(add2(pB, qB)));
    }

    ull a2A[12], a2B[12];
#pragma unroll
    for (int k = 0; k < 12; k++) {
        a2A[k] = pack2(aA[2 * k], aA[2 * k + 1]);
        a2B[k] = pack2(aB[2 * k], aB[2 * k + 1]);
    }

    float4* outA = (float4*)(g_xg + rA * G3);
    float4* outB = (float4*)(g_xg + rB * G3);
#pragma unroll
    for (int g4 = 0; g4 < 18; g4++) {
        float oA[4], oB[4];
#pragma unroll
        for (int s = 0; s < 4; s++) {
            int g = g4 * 4 + s;
            const ulonglong2* w2 = (const ulonglong2*)&s_wi2[g * 12];
            float b = s_cb[g];
            ull pA = pack2(b, 0.0f), qA = 0ULL, pB = pack2(b, 0.0f), qB = 0ULL;
#pragma unroll
            for (int m = 0; m < 6; m++) {
                ulonglong2 w = w2[m];
                pA = fma2(w.x, a2A[2 * m], pA);
                qA = fma2(w.y, a2A[2 * m + 1], qA);
                pB = fma2(w.x, a2B[2 * m], pB);
                qB = fma2(w.y, a2B[2 * m + 1], qB);
            }
            oA[s] = hsum2(add2(pA, qA));
            oB[s] = hsum2(add2(pB, qB));
        }
        outA[g4] = make_float4(oA[0], oA[1], oA[2], oA[3]);
        outB[g4] = make_float4(oB[0], oB[1], oB[2], oB[3]);
    }

    // publish: all stores visible, then raise flag[t]
    __threadfence();
    __syncthreads();
    if (tid == 0) *(volatile unsigned char*)&g_flag[t] = 1;
}

// ---------------------------------------------------------------------------
// Phase 3: out[b,t] = sigmoid(lc2_w . h[b,t,:] + lc2_b). One thread per row.
// ---------------------------------------------------------------------------
__global__ __launch_bounds__(256) void vad_phase3(
    const float* __restrict__ lc2_w, const float* __restrict__ lc2_b,
    float* __restrict__ out)
{
    size_t idx = (size_t)blockIdx.x * 256 + threadIdx.x;
    const float4* hv = (const float4*)(g_h + idx * HH);
    const float4* wv = (const float4*)lc2_w;

    ull acc = pack2(0.5f * lc2_b[0], 0.0f);
#pragma unroll
    for (int q = 0; q < 6; q++) {
        float4 hq = hv[q];
        float4 wq = __ldg(&wv[q]);
        acc = fma2(pack2(hq.x, hq.y), pack2(0.5f * wq.x, 0.5f * wq.y), acc);
        acc = fma2(pack2(hq.z, hq.w), pack2(0.5f * wq.z, 0.5f * wq.w), acc);
    }
    out[idx] = fmaf(tanh_a(hsum2(acc)), 0.5f, 0.5f);
}

extern "C" void kernel_launch(void* const* d_in, const int* in_sizes, int n_in,
                              void* d_out, int out_size) {
    const float* x     = (const float*)d_in[0];
    const float* lc1_w = (const float*)d_in[1];
    const float* lc1_b = (const float*)d_in[2];
    const float* w_ih  = (const float*)d_in[3];
    const float* w_hh  = (const float*)d_in[4];
    const float* b_ih  = (const float*)d_in[5];
    const float* b_hh  = (const float*)d_in[6];
    const float* lc2_w = (const float*)d_in[7];
    const float* lc2_b = (const float*)d_in[8];
    float* out = (float*)d_out;

    vad_zero<<<1, 512>>>();
    vad_fused<<<PH2B + TT, 128>>>(x, lc1_w, lc1_b, w_ih, b_ih, w_hh, b_hh);
    vad_phase3<<<ROWS / 256, 256>>>(lc2_w, lc2_b, out);
}

// round 8
// speedup vs baseline: 1.0467x; 1.0467x over previous
#include <cuda_runtime.h>

typedef unsigned long long ull;

#define BB   256
#define TT   2000
#define FIN  42
#define FINP 44
#define HH   24
#define G3   72
#define ROWS (BB * TT)
#define UU   8
#define PH2B 64
#define TCH  125          // timesteps per producer chunk
#define NCH  (TT / TCH)   // 16 chunks
#define NBP  (BB / 2)     // 128 batch-pairs per chunk

// scratch: xg[row][72] gate preacts (147.5 MB), h[B,T,24] (49 MB), counters
__device__ float g_xg[(size_t)ROWS * G3];
__device__ float g_h[(size_t)ROWS * HH];
__device__ int g_cnt[NCH];

__device__ __forceinline__ float tanh_a(float x) {
    float y; asm("tanh.approx.f32 %0, %1;" : "=f"(y) : "f"(x)); return y;
}
__device__ __forceinline__ ull fma2(ull a, ull b, ull c) {
    ull d; asm("fma.rn.f32x2 %0, %1, %2, %3;" : "=l"(d) : "l"(a), "l"(b), "l"(c)); return d;
}
__device__ __forceinline__ ull add2(ull a, ull b) {
    ull d; asm("add.rn.f32x2 %0, %1, %2;" : "=l"(d) : "l"(a), "l"(b)); return d;
}
__device__ __forceinline__ ull pack2(float lo, float hi) {
    ull d; asm("mov.b64 %0, {%1, %2};" : "=l"(d) : "f"(lo), "f"(hi)); return d;
}
__device__ __forceinline__ float2 unpack2(ull v) {
    float2 r; asm("mov.b64 {%0, %1}, %2;" : "=f"(r.x), "=f"(r.y) : "l"(v)); return r;
}
__device__ __forceinline__ float hsum2(ull v) {
    float2 r = unpack2(v); return r.x + r.y;
}
__device__ __forceinline__ int ld_acq_i(const int* p) {
    int v; asm volatile("ld.acquire.gpu.global.s32 %0, [%1];" : "=r"(v) : "l"(p) : "memory");
    return v;
}
__device__ __forceinline__ void red_rel_i(int* p) {
    asm volatile("red.release.gpu.global.add.s32 [%0], 1;" :: "l"(p) : "memory");
}
__device__ __forceinline__ void wait_cnt(const int* p) {
    while (ld_acq_i(p) != NBP) __nanosleep(64);
}

__global__ void vad_zero() {
    int i = threadIdx.x + blockIdx.x * blockDim.x;
    if (i < NCH) g_cnt[i] = 0;
}

// ---------------------------------------------------------------------------
// Fused kernel. Blocks [0,64): consumers (4 GRU warps, one batch row each).
// Blocks [64, 64+2048): producers — block handles 2 batches x 125 consecutive
// timesteps (fully coalesced x reads), chunk-major order, release-counter per
// chunk when done. Consumers never block producers (they occupy only 64 of
// the ~296 co-resident block slots), so forward progress is guaranteed.
// ---------------------------------------------------------------------------
__global__ __launch_bounds__(128) void vad_fused(
    const float* __restrict__ x, const float* __restrict__ lc1_w,
    const float* __restrict__ lc1_b, const float* __restrict__ w_ih,
    const float* __restrict__ b_ih, const float* __restrict__ w_hh,
    const float* __restrict__ b_hh)
{
    __shared__ __align__(16) float s_w1[HH * FINP];
    __shared__ float s_b1[HH];
    __shared__ __align__(16) ull s_wi2[G3 * 12];
    __shared__ float s_cb[G3];
    __shared__ __align__(16) float s_h[4][2][32];

    int tid = threadIdx.x;

    if (blockIdx.x < PH2B) {
        // ---------------- consumer: GRU recurrence ----------------
        int wid = tid >> 5, lane = tid & 31;
        int b = blockIdx.x * 4 + wid;
        int i = (lane < HH) ? lane : 0;

        const ull* w8 = (const ull*)w_hh;
        ull wr2[12], wz2[12], wn2[12];
#pragma unroll
        for (int k = 0; k < 12; k++) {
            float2 r = unpack2(w8[(0 * HH + i) * 12 + k]);
            wr2[k] = pack2(0.5f * r.x, 0.5f * r.y);
            float2 z = unpack2(w8[(1 * HH + i) * 12 + k]);
            wz2[k] = pack2(0.5f * z.x, 0.5f * z.y);
            wn2[k] = w8[(2 * HH + i) * 12 + k];
        }
        ull bn2 = pack2(b_hh[2 * HH + i], 0.0f);

        const float* xgp = g_xg + (size_t)b * TT * G3;
        float* hp = g_h + (size_t)b * TT * HH;

        wait_cnt(&g_cnt[0]);   // t in [0, 125) ready

        float h = 0.0f;
        float cr[UU], cz[UU], cn[UU];
#pragma unroll
        for (int u = 0; u < UU; u++) {
            cr[u] = __ldcg(xgp + u * G3 + 0 * HH + i);
            cz[u] = __ldcg(xgp + u * G3 + 1 * HH + i);
            cn[u] = __ldcg(xgp + u * G3 + 2 * HH + i);
        }

        for (int t0 = 0; t0 < TT; t0 += UU) {
            // prefetch next chunk (readiness confirmed last iteration)
            float nr[UU], nz[UU], nn[UU];
            bool more = (t0 + UU) < TT;
            const float* np = xgp + (size_t)(t0 + UU) * G3;
#pragma unroll
            for (int u = 0; u < UU; u++) {
                nr[u] = more ? __ldcg(np + u * G3 + 0 * HH + i) : 0.0f;
                nz[u] = more ? __ldcg(np + u * G3 + 1 * HH + i) : 0.0f;
                nn[u] = more ? __ldcg(np + u * G3 + 2 * HH + i) : 0.0f;
            }

            // early acquire-read of the chunk counter guarding NEXT
            // iteration's prefetch; branch-checked after the compute below.
            bool need = (t0 + 2 * UU) < TT;
            int ch = (t0 + 2 * UU + UU - 1) / TCH;
            int f = need ? ld_acq_i(&g_cnt[ch]) : NBP;

#pragma unroll
            for (int u = 0; u < UU; u++) {
                int pb = u & 1;
                s_h[wid][pb][lane] = h;
                __syncwarp();
                ull h2[12];
                {
                    const ulonglong2* sh2 = (const ulonglong2*)&s_h[wid][pb][0];
#pragma unroll
                    for (int k = 0; k < 6; k++) {
                        ulonglong2 t = sh2[k];
                        h2[2 * k] = t.x; h2[2 * k + 1] = t.y;
                    }
                }
                ull ra = pack2(cr[u], 0.0f), rb = 0ULL;
                ull za = pack2(cz[u], 0.0f), zb = 0ULL;
                ull na = bn2, nb2 = 0ULL;
#pragma unroll
                for (int m = 0; m < 6; m++) {
                    ra  = fma2(wr2[2 * m],     h2[2 * m],     ra);
                    rb  = fma2(wr2[2 * m + 1], h2[2 * m + 1], rb);
                    za  = fma2(wz2[2 * m],     h2[2 * m],     za);
                    zb  = fma2(wz2[2 * m + 1], h2[2 * m + 1], zb);
                    na  = fma2(wn2[2 * m],     h2[2 * m],     na);
                    nb2 = fma2(wn2[2 * m + 1], h2[2 * m + 1], nb2);
                }
                float hr = hsum2(add2(ra, rb));
                float hz = hsum2(add2(za, zb));
                float hn = hsum2(add2(na, nb2));

                float r = fmaf(tanh_a(hr), 0.5f, 0.5f);
                float z = fmaf(tanh_a(hz), 0.5f, 0.5f);
                float n = tanh_a(fmaf(r, hn, cn[u]));
                h = fmaf(z, h - n, n);

                if (lane < HH) hp[(t0 + u) * HH + lane] = h;
            }

            if (need && f != NBP) wait_cnt(&g_cnt[ch]);

#pragma unroll
            for (int u = 0; u < UU; u++) { cr[u] = nr[u]; cz[u] = nz[u]; cn[u] = nn[u]; }
        }
        return;
    }

    // ---------------- producer: 2 batches x 125 timesteps ----------------
    int pid = blockIdx.x - PH2B;
    int c  = pid >> 7;          // chunk (completed in ascending order)
    int bp = pid & 127;         // batch pair

    for (int i = tid; i < HH * FINP; i += 128) {
        int h = i / FINP, f = i - h * FINP;
        s_w1[i] = (f < FIN) ? lc1_w[h * FIN + f] : 0.0f;
    }
    const ull* wi8 = (const ull*)w_ih;
    for (int i = tid; i < G3 * 12; i += 128) {
        ull w = wi8[i];
        if (i < 48 * 12) {                 // r,z rows pre-halved
            float2 f = unpack2(w);
            w = pack2(0.5f * f.x, 0.5f * f.y);
        }
        s_wi2[i] = w;
    }
    if (tid < G3) {
        float b = b_ih[tid];
        s_cb[tid] = (tid < 48) ? 0.5f * (b + b_hh[tid]) : b;
    }
    if (tid < HH) s_b1[tid] = lc1_b[tid];
    __syncthreads();

    if (tid < TCH) {
        int t = c * TCH + tid;
        size_t rA = (size_t)(2 * bp) * TT + t;       // rows contiguous across
        size_t rB = (size_t)(2 * bp + 1) * TT + t;   // threads -> coalesced
        const ull* xA = (const ull*)(x + rA * FIN);
        const ull* xB = (const ull*)(x + rB * FIN);

        ull xpA[22], xpB[22];
#pragma unroll
        for (int q = 0; q < 21; q++) { xpA[q] = xA[q]; xpB[q] = xB[q]; }
        xpA[21] = 0ULL; xpB[21] = 0ULL;

        float aA[HH], aB[HH];
#pragma unroll
        for (int h = 0; h < HH; h++) {
            const ulonglong2* wv = (const ulonglong2*)&s_w1[h * FINP];
            float b = s_b1[h];
            ull pA = pack2(b, 0.0f), qA = 0ULL, pB = pack2(b, 0.0f), qB = 0ULL;
#pragma unroll
            for (int m = 0; m < 11; m++) {
                ulonglong2 w = wv[m];
                pA = fma2(w.x, xpA[2 * m], pA);
                qA = fma2(w.y, xpA[2 * m + 1], qA);
                pB = fma2(w.x, xpB[2 * m], pB);
                qB = fma2(w.y, xpB[2 * m + 1], qB);
            }
            aA[h] = tanh_a(hsum2(add2(pA, qA)));
            aB[h] = tanh_a(hsum2(add2(pB, qB)));
        }

        ull a2A[12], a2B[12];
#pragma unroll
        for (int k = 0; k < 12; k++) {
            a2A[k] = pack2(aA[2 * k], aA[2 * k + 1]);
            a2B[k] = pack2(aB[2 * k], aB[2 * k + 1]);
        }

        float4* outA = (float4*)(g_xg + rA * G3);
        float4* outB = (float4*)(g_xg + rB * G3);
#pragma unroll
        for (int g4 = 0; g4 < 18; g4++) {
            float oA[4], oB[4];
#pragma unroll
            for (int s = 0; s < 4; s++) {
                int g = g4 * 4 + s;
                const ulonglong2* w2 = (const ulonglong2*)&s_wi2[g * 12];
                float b = s_cb[g];
                ull pA = pack2(b, 0.0f), qA = 0ULL, pB = pack2(b, 0.0f), qB = 0ULL;
#pragma unroll
                for (int m = 0; m < 6; m++) {
                    ulonglong2 w = w2[m];
                    pA = fma2(w.x, a2A[2 * m], pA);
                    qA = fma2(w.y, a2A[2 * m + 1], qA);
                    pB = fma2(w.x, a2B[2 * m], pB);
                    qB = fma2(w.y, a2B[2 * m + 1], qB);
                }
                oA[s] = hsum2(add2(pA, qA));
                oB[s] = hsum2(add2(pB, qB));
            }
            outA[g4] = make_float4(oA[0], oA[1], oA[2], oA[3]);
            outB[g4] = make_float4(oB[0], oB[1], oB[2], oB[3]);
        }
    }

    // publish chunk: all stores visible, then release-increment counter
    __threadfence();
    __syncthreads();
    if (tid == 0) red_rel_i(&g_cnt[c]);
}

// ---------------------------------------------------------------------------
// Phase 3: out[b,t] = sigmoid(lc2_w . h[b,t,:] + lc2_b). One thread per row.
// ---------------------------------------------------------------------------
__global__ __launch_bounds__(256) void vad_phase3(
    const float* __restrict__ lc2_w, const float* __restrict__ lc2_b,
    float* __restrict__ out)
{
    size_t idx = (size_t)blockIdx.x * 256 + threadIdx.x;
    const float4* hv = (const float4*)(g_h + idx * HH);
    const float4* wv = (const float4*)lc2_w;

    ull acc = pack2(0.5f * lc2_b[0], 0.0f);
#pragma unroll
    for (int q = 0; q < 6; q++) {
        float4 hq = hv[q];
        float4 wq = __ldg(&wv[q]);
        acc = fma2(pack2(hq.x, hq.y), pack2(0.5f * wq.x, 0.5f * wq.y), acc);
        acc = fma2(pack2(hq.z, hq.w), pack2(0.5f * wq.z, 0.5f * wq.w), acc);
    }
    out[idx] = fmaf(tanh_a(hsum2(acc)), 0.5f, 0.5f);
}

extern "C" void kernel_launch(void* const* d_in, const int* in_sizes, int n_in,
                              void* d_out, int out_size) {
    const float* x     = (const float*)d_in[0];
    const float* lc1_w = (const float*)d_in[1];
    const float* lc1_b = (const float*)d_in[2];
    const float* w_ih  = (const float*)d_in[3];
    const float* w_hh  = (const float*)d_in[4];
    const float* b_ih  = (const float*)d_in[5];
    const float* b_hh  = (const float*)d_in[6];
    const float* lc2_w = (const float*)d_in[7];
    const float* lc2_b = (const float*)d_in[8];
    float* out = (float*)d_out;

    vad_zero<<<1, 32>>>();
    vad_fused<<<PH2B + NCH * NBP, 128>>>(x, lc1_w, lc1_b, w_ih, b_ih, w_hh, b_hh);
    vad_phase3<<<ROWS / 256, 256>>>(lc2_w, lc2_b, out);
}

// round 9
// speedup vs baseline: 1.3038x; 1.2456x over previous
#include <cuda_runtime.h>

typedef unsigned long long ull;

#define BB   256
#define TT   2000
#define FIN  42
#define FINP 44
#define HH   24
#define G3   72
#define ROWS (BB * TT)
#define UU   8

// scratch: xg[row][72] gate preacts (147.5 MB), h[B,T,24] (49 MB)
__device__ float g_xg[(size_t)ROWS * G3];
__device__ float g_h[(size_t)ROWS * HH];

__device__ __forceinline__ float tanh_a(float x) {
    float y; asm("tanh.approx.f32 %0, %1;" : "=f"(y) : "f"(x)); return y;
}
__device__ __forceinline__ ull fma2(ull a, ull b, ull c) {
    ull d; asm("fma.rn.f32x2 %0, %1, %2, %3;" : "=l"(d) : "l"(a), "l"(b), "l"(c)); return d;
}
__device__ __forceinline__ ull add2(ull a, ull b) {
    ull d; asm("add.rn.f32x2 %0, %1, %2;" : "=l"(d) : "l"(a), "l"(b)); return d;
}
__device__ __forceinline__ ull pack2(float lo, float hi) {
    ull d; asm("mov.b64 %0, {%1, %2};" : "=l"(d) : "f"(lo), "f"(hi)); return d;
}
__device__ __forceinline__ float2 unpack2(ull v) {
    float2 r; asm("mov.b64 {%0, %1}, %2;" : "=f"(r.x), "=f"(r.y) : "l"(v)); return r;
}
__device__ __forceinline__ float hsum2(ull v) {
    float2 r = unpack2(v); return r.x + r.y;
}
// ordered shared ops (converged-warp broadcast; no syncwarp needed since the
// in-order LSU services the warp's STS before its subsequent LDS)
__device__ __forceinline__ void sts_f32(unsigned addr, float v) {
    asm volatile("st.shared.f32 [%0], %1;" :: "r"(addr), "f"(v) : "memory");
}
__device__ __forceinline__ void lds_v4(unsigned addr, ull& a, ull& b) {
    asm volatile("ld.shared.v4.b32 {%0, %1, %2, %3}, [%4];"
                 : "=r"(*(unsigned*)&a), "=r"(((unsigned*)&a)[1]),
                   "=r"(*(unsigned*)&b), "=r"(((unsigned*)&b)[1])
                 : "r"(addr) : "memory");
}

// ---------------------------------------------------------------------------
// Phase 1: compact [row][72] layout. 2 rows/thread; x direct from global
// (LDG.64, coalesced). Biases folded: r/z entries stored as
// 0.5*(x-side + b_hh) with W rows pre-halved; n entries plain x-side + b_ih.
// ---------------------------------------------------------------------------
__global__ __launch_bounds__(128) void vad_phase1(
    const float* __restrict__ x, const float* __restrict__ lc1_w,
    const float* __restrict__ lc1_b, const float* __restrict__ w_ih,
    const float* __restrict__ b_ih, const float* __restrict__ b_hh)
{
    __shared__ __align__(16) float s_w1[HH * FINP];
    __shared__ float s_b1[HH];
    __shared__ __align__(16) ull s_wi2[G3 * 12];
    __shared__ float s_cb[G3];

    int tid = threadIdx.x;
    for (int i = tid; i < HH * FINP; i += 128) {
        int h = i / FINP, f = i - h * FINP;
        s_w1[i] = (f < FIN) ? lc1_w[h * FIN + f] : 0.0f;
    }
    const ull* wi8 = (const ull*)w_ih;
    for (int i = tid; i < G3 * 12; i += 128) {
        ull w = wi8[i];
        if (i < 48 * 12) {                 // r,z rows pre-halved
            float2 f = unpack2(w);
            w = pack2(0.5f * f.x, 0.5f * f.y);
        }
        s_wi2[i] = w;
    }
    if (tid < G3) {
        float b = b_ih[tid];
        s_cb[tid] = (tid < 48) ? 0.5f * (b + b_hh[tid]) : b;
    }
    if (tid < HH) s_b1[tid] = lc1_b[tid];
    __syncthreads();

    size_t r0 = (size_t)blockIdx.x * 256;
    const ull* xA = (const ull*)(x + (r0 + tid) * FIN);
    const ull* xB = (const ull*)(x + (r0 + 128 + tid) * FIN);

    ull xpA[22], xpB[22];
#pragma unroll
    for (int q = 0; q < 21; q++) { xpA[q] = xA[q]; xpB[q] = xB[q]; }
    xpA[21] = 0ULL; xpB[21] = 0ULL;

    float aA[HH], aB[HH];
#pragma unroll
    for (int h = 0; h < HH; h++) {
        const ulonglong2* wv = (const ulonglong2*)&s_w1[h * FINP];
        float b = s_b1[h];
        ull pA = pack2(b, 0.0f), qA = 0ULL, pB = pack2(b, 0.0f), qB = 0ULL;
#pragma unroll
        for (int m = 0; m < 11; m++) {
            ulonglong2 w = wv[m];
            pA = fma2(w.x, xpA[2 * m], pA);
            qA = fma2(w.y, xpA[2 * m + 1], qA);
            pB = fma2(w.x, xpB[2 * m], pB);
            qB = fma2(w.y, xpB[2 * m + 1], qB);
        }
        aA[h] = tanh_a(hsum2(add2(pA, qA)));
        aB[h] = tanh_a(hsum2(add2(pB, qB)));
    }

    ull a2A[12], a2B[12];
#pragma unroll
    for (int k = 0; k < 12; k++) {
        a2A[k] = pack2(aA[2 * k], aA[2 * k + 1]);
        a2B[k] = pack2(aB[2 * k], aB[2 * k + 1]);
    }

    float4* outA = (float4*)(g_xg + (r0 + tid) * G3);
    float4* outB = (float4*)(g_xg + (r0 + 128 + tid) * G3);
#pragma unroll
    for (int g4 = 0; g4 < 18; g4++) {
        float oA[4], oB[4];
#pragma unroll
        for (int s = 0; s < 4; s++) {
            int g = g4 * 4 + s;
            const ulonglong2* w2 = (const ulonglong2*)&s_wi2[g * 12];
            float b = s_cb[g];
            ull pA = pack2(b, 0.0f), qA = 0ULL, pB = pack2(b, 0.0f), qB = 0ULL;
#pragma unroll
            for (int m = 0; m < 6; m++) {
                ulonglong2 w = w2[m];
                pA = fma2(w.x, a2A[2 * m], pA);
                qA = fma2(w.y, a2A[2 * m + 1], qA);
                pB = fma2(w.x, a2B[2 * m], pB);
                qB = fma2(w.y, a2B[2 * m + 1], qB);
            }
            oA[s] = hsum2(add2(pA, qA));
            oB[s] = hsum2(add2(pB, qB));
        }
        outA[g4] = make_float4(oA[0], oA[1], oA[2], oA[3]);
        outB[g4] = make_float4(oB[0], oB[1], oB[2], oB[3]);
    }
}

// ---------------------------------------------------------------------------
// Phase 2: GRU recurrence. One warp per batch row; h[i] in lane i.
// Sync-free double-buffered shared broadcast (converged warp, asm-ordered).
// ---------------------------------------------------------------------------
__global__ __launch_bounds__(32) void vad_phase2(
    const float* __restrict__ w_hh, const float* __restrict__ b_hh)
{
    __shared__ __align__(16) float s_h[2][32];
    int lane = threadIdx.x;
    int b = blockIdx.x;
    int i = (lane < HH) ? lane : 0;

    unsigned sbase;
    asm("{ .reg .u64 t; cvta.to.shared.u64 t, %1; cvt.u32.u64 %0, t; }"
        : "=r"(sbase) : "l"(&s_h[0][0]));
    unsigned st0 = sbase + lane * 4, st1 = sbase + 128 + lane * 4;

    const ull* w8 = (const ull*)w_hh;
    ull wr2[12], wz2[12], wn2[12];
#pragma unroll
    for (int k = 0; k < 12; k++) {
        float2 r = unpack2(w8[(0 * HH + i) * 12 + k]);
        wr2[k] = pack2(0.5f * r.x, 0.5f * r.y);
        float2 z = unpack2(w8[(1 * HH + i) * 12 + k]);
        wz2[k] = pack2(0.5f * z.x, 0.5f * z.y);
        wn2[k] = w8[(2 * HH + i) * 12 + k];
    }
    ull bn2 = pack2(b_hh[2 * HH + i], 0.0f);

    const float* xgp = g_xg + (size_t)b * TT * G3;
    float* hp = g_h + (size_t)b * TT * HH;

    float h = 0.0f;
    float cr[UU], cz[UU], cn[UU];
#pragma unroll
    for (int u = 0; u < UU; u++) {
        cr[u] = __ldcg(xgp + u * G3 + 0 * HH + i);
        cz[u] = __ldcg(xgp + u * G3 + 1 * HH + i);
        cn[u] = __ldcg(xgp + u * G3 + 2 * HH + i);
    }

    for (int t0 = 0; t0 < TT; t0 += UU) {
        float nr[UU], nz[UU], nn[UU];
        bool more = (t0 + UU) < TT;
        const float* np = xgp + (size_t)(t0 + UU) * G3;
#pragma unroll
        for (int u = 0; u < UU; u++) {
            nr[u] = more ? __ldcg(np + u * G3 + 0 * HH + i) : 0.0f;
            nz[u] = more ? __ldcg(np + u * G3 + 1 * HH + i) : 0.0f;
            nn[u] = more ? __ldcg(np + u * G3 + 2 * HH + i) : 0.0f;
        }

#pragma unroll
        for (int u = 0; u < UU; u++) {
            unsigned stw = (u & 1) ? st1 : st0;
            unsigned ldb = (u & 1) ? sbase + 128 : sbase;
            sts_f32(stw, h);                 // converged warp: ordered before LDS
            ull h2[12];
#pragma unroll
            for (int k = 0; k < 6; k++)
                lds_v4(ldb + k * 16, h2[2 * k], h2[2 * k + 1]);

            ull ra = pack2(cr[u], 0.0f), rb = 0ULL;
            ull za = pack2(cz[u], 0.0f), zb = 0ULL;
            ull na = bn2, nb2 = 0ULL;
#pragma unroll
            for (int m = 0; m < 6; m++) {
                ra  = fma2(wr2[2 * m],     h2[2 * m],     ra);
                rb  = fma2(wr2[2 * m + 1], h2[2 * m + 1], rb);
                za  = fma2(wz2[2 * m],     h2[2 * m],     za);
                zb  = fma2(wz2[2 * m + 1], h2[2 * m + 1], zb);
                na  = fma2(wn2[2 * m],     h2[2 * m],     na);
                nb2 = fma2(wn2[2 * m + 1], h2[2 * m + 1], nb2);
            }
            float hr = hsum2(add2(ra, rb));
            float hz = hsum2(add2(za, zb));
            float hn = hsum2(add2(na, nb2));

            float r = fmaf(tanh_a(hr), 0.5f, 0.5f);
            float z = fmaf(tanh_a(hz), 0.5f, 0.5f);
            float n = tanh_a(fmaf(r, hn, cn[u]));
            h = fmaf(z, h - n, n);

            if (lane < HH) hp[(t0 + u) * HH + lane] = h;
        }

#pragma unroll
        for (int u = 0; u < UU; u++) { cr[u] = nr[u]; cz[u] = nz[u]; cn[u] = nn[u]; }
    }
}

// ---------------------------------------------------------------------------
// Phase 3: out[b,t] = sigmoid(lc2_w . h[b,t,:] + lc2_b). One thread per row.
// ---------------------------------------------------------------------------
__global__ __launch_bounds__(256) void vad_phase3(
    const float* __restrict__ lc2_w, const float* __restrict__ lc2_b,
    float* __restrict__ out)
{
    size_t idx = (size_t)blockIdx.x * 256 + threadIdx.x;
    const float4* hv = (const float4*)(g_h + idx * HH);
    const float4* wv = (const float4*)lc2_w;

    ull acc = pack2(0.5f * lc2_b[0], 0.0f);
#pragma unroll
    for (int q = 0; q < 6; q++) {
        float4 hq = hv[q];
        float4 wq = __ldg(&wv[q]);
        acc = fma2(pack2(hq.x, hq.y), pack2(0.5f * wq.x, 0.5f * wq.y), acc);
        acc = fma2(pack2(hq.z, hq.w), pack2(0.5f * wq.z, 0.5f * wq.w), acc);
    }
    out[idx] = fmaf(tanh_a(hsum2(acc)), 0.5f, 0.5f);
}

extern "C" void kernel_launch(void* const* d_in, const int* in_sizes, int n_in,
                              void* d_out, int out_size) {
    const float* x     = (const float*)d_in[0];
    const float* lc1_w = (const float*)d_in[1];
    const float* lc1_b = (const float*)d_in[2];
    const float* w_ih  = (const float*)d_in[3];
    const float* w_hh  = (const float*)d_in[4];
    const float* b_ih  = (const float*)d_in[5];
    const float* b_hh  = (const float*)d_in[6];
    const float* lc2_w = (const float*)d_in[7];
    const float* lc2_b = (const float*)d_in[8];
    float* out = (float*)d_out;

    vad_phase1<<<ROWS / 256, 128>>>(x, lc1_w, lc1_b, w_ih, b_ih, b_hh);
    vad_phase2<<<BB, 32>>>(w_hh, b_hh);
    vad_phase3<<<ROWS / 256, 256>>>(lc2_w, lc2_b, out);
}